// round 5
// baseline (speedup 1.0000x reference)
#include <cuda_runtime.h>
#include <math.h>
#include <stdint.h>

#define NN     8192
#define NB     8192
#define RANGEF 74000.0f
#define INV_W  ((float)NB / RANGEF)
#define GRID   128
#define TPB    1024

// Scratch (__device__ globals; zero-initialized at load; all state is
// self-restoring so every graph replay sees the same initial state).
__device__ float g_A[NN];          // edge segment sums (starts 0, reset in phase S)
__device__ float g_S[NN];          // S per node (original order)
__device__ float g_V[NN];          // bucket-grouped copy of S
__device__ int   g_P[NB + 1];      // exclusive prefix of bucket histogram
__device__ float g_C;              // dot(x, p)

// Software grid barrier state (3 slots, each self-resetting via departure count)
__device__ int          g_cnt[3];
__device__ int          g_dep[3];
__device__ volatile int g_rel[3];

__device__ __forceinline__ void gbar(int b) {
    __syncthreads();
    if (threadIdx.x == 0) {
        __threadfence();                       // publish this block's writes
        if (atomicAdd(&g_cnt[b], 1) == GRID - 1) {
            g_rel[b] = 1;                      // release
            __threadfence();
        } else {
            while (g_rel[b] == 0) __nanosleep(64);
        }
        __threadfence();                       // acquire others' writes
        if (atomicAdd(&g_dep[b], 1) == GRID - 1) {
            g_cnt[b] = 0;                      // all blocks have departed:
            g_dep[b] = 0;                      // safe to reset for next replay
            __threadfence();
            g_rel[b] = 0;
        }
    }
    __syncthreads();
}

// Monotone bucket map. MUST be identical at insert and query.
__device__ __forceinline__ int bucket_of(float v, float C) {
    float u = (v - C) * INV_W;
    int b = (int)u;
    if (b < 0) b = 0;
    if (b > NB - 1) b = NB - 1;
    return b;
}

// ---------------------------------------------------------------------------
__global__ void __launch_bounds__(TPB, 1)
fused(const int* __restrict__ ei, const float* __restrict__ p,
      const float* __restrict__ x, float* __restrict__ out,
      int E, int n, float logn) {

    __shared__ int cnt[NB];        // build: histogram -> prefix -> counters
    __shared__ int wsum[32];       // build: warp scan workspace
    __shared__ double dsh[TPB];    // dot workspace (block 0 only)

    const int t = threadIdx.x;
    const int b = blockIdx.x;

    // ---------------- Phase 1: edges (blocks 1..) + dot (block 0) ----------
    if (b == 0) {
        double acc = 0.0;
        for (int i = t; i < n; i += TPB)
            acc += (double)x[i] * (double)p[i];
        dsh[t] = acc;
        __syncthreads();
        for (int s = TPB / 2; s > 0; s >>= 1) {
            if (t < s) dsh[t] += dsh[t + s];
            __syncthreads();
        }
        if (t == 0) g_C = (float)dsh[0];
    } else {
        const int nthr = (GRID - 1) * TPB;
        const int tid  = (b - 1) * TPB + t;
        if ((E & 3) == 0 && (((unsigned long long)ei) & 15ull) == 0) {
            const int E4 = E >> 2;
            const int4* s4 = (const int4*)ei;
            const int4* d4 = (const int4*)(ei + E);
            for (int j = tid; j < E4; j += nthr) {
                int4 s = __ldg(&s4[j]);
                int4 d = __ldg(&d4[j]);
                float p0 = __ldg(&p[s.x]);
                float p1 = __ldg(&p[s.y]);
                float p2 = __ldg(&p[s.z]);
                float p3 = __ldg(&p[s.w]);
                atomicAdd(&g_A[d.x], p0);
                atomicAdd(&g_A[d.y], p1);
                atomicAdd(&g_A[d.z], p2);
                atomicAdd(&g_A[d.w], p3);
            }
        } else {
            for (int e = tid; e < E; e += nthr) {
                int s = __ldg(&ei[e]);
                int d = __ldg(&ei[E + e]);
                atomicAdd(&g_A[d], __ldg(&p[s]));
            }
        }
    }
    gbar(0);

    // ---------------- Phase 2a: S distributed across all blocks -----------
    // Each block owns 64 nodes: i = b*64 + t  (t < 64). Keep Si in register
    // for the output phase (same i-to-thread mapping).
    float C  = g_C;
    float Si = 0.0f;
    int   myI = b * (NN / GRID) + t;
    bool  mine = (t < NN / GRID) && (myI < n);
    if (mine) {
        float A  = g_A[myI];
        g_A[myI] = 0.0f;                       // restore invariant
        float pi = __ldg(&p[myI]);
        Si = pi * logn + logf(pi + A) + C;
        g_S[myI] = Si;
    }
    gbar(1);

    // ---------------- Phase 2b: build (block 0 only) ----------------------
    if (b == 0) {
#pragma unroll
        for (int k = 0; k < NB / TPB; k++) cnt[t + TPB * k] = 0;
        __syncthreads();

        float sv[NN / TPB];
        int   bk[NN / TPB];
#pragma unroll
        for (int k = 0; k < NN / TPB; k++) {
            int i = t + TPB * k;
            float s = g_S[i];
            sv[k] = s;
            int bb = bucket_of(s, C);
            bk[k] = bb;
            atomicAdd(&cnt[bb], 1);
        }
        __syncthreads();

        // Exclusive scan over 8192 bins: 8 serial per thread + shuffle scan.
        int base = t * 8;
        int ex[8];
        int tot = 0;
#pragma unroll
        for (int k = 0; k < 8; k++) { ex[k] = tot; tot += cnt[base + k]; }

        int lane = t & 31, wid = t >> 5;
        int v = tot;
#pragma unroll
        for (int o = 1; o < 32; o <<= 1) {
            int u = __shfl_up_sync(0xffffffffu, v, o);
            if (lane >= o) v += u;
        }
        if (lane == 31) wsum[wid] = v;
        __syncthreads();
        if (wid == 0) {
            int w = wsum[lane];
#pragma unroll
            for (int o = 1; o < 32; o <<= 1) {
                int u = __shfl_up_sync(0xffffffffu, w, o);
                if (lane >= o) w += u;
            }
            wsum[lane] = w;
        }
        __syncthreads();
        int excl = v - tot + (wid ? wsum[wid - 1] : 0);

#pragma unroll
        for (int k = 0; k < 8; k++) {
            int pref = excl + ex[k];
            cnt[base + k] = pref;              // live counters for scatter
            g_P[base + k] = pref;              // published prefix
        }
        if (t == TPB - 1) g_P[NB] = excl + tot;
        __syncthreads();

#pragma unroll
        for (int k = 0; k < NN / TPB; k++) {
            int pos = atomicAdd(&cnt[bk[k]], 1);
            g_V[pos] = sv[k];
        }
    }
    gbar(2);

    // ---------------- Phase 3: output ---------------------------------
    // out[i] = sum_j tanh(1000*(S_i - S_j) - 5). Outside band
    // [Si-0.015, Si+0.005]: exactly saturated (+1/-1) -> prefix counts.
    // Band buckets: exact per-element evaluation (incl. diagonal j=i).
    if (mine) {
        const float K   = 1000.0f;
        const float EPS = 5.0f;
        const float CUT = 10.0f;

        int loB = bucket_of(Si - 0.015f, C);
        int hiB = bucket_of(Si + 0.005f, C);

        int pLo = g_P[loB];
        int pHi = g_P[hiB + 1];
        float acc = (float)pLo - (float)(n - pHi);

        for (int idx = pLo; idx < pHi; ++idx) {
            float w   = g_V[idx];
            float arg = K * (Si - w) - EPS;
            if (arg > CUT)        acc += 1.0f;
            else if (arg < -CUT)  acc -= 1.0f;
            else                  acc += tanhf(arg);
        }
        out[myI] = acc;
    }
}

// ---------------------------------------------------------------------------
extern "C" void kernel_launch(void* const* d_in, const int* in_sizes, int n_in,
                              void* d_out, int out_size) {
    const int*   ei = (const int*)d_in[0];     // (2, E) row-major
    const float* p  = (const float*)d_in[1];   // (N,)
    const float* x  = (const float*)d_in[2];   // (N, 1)

    int E = in_sizes[0] / 2;
    int n = in_sizes[1];
    float logn = logf((float)n);

    fused<<<GRID, TPB>>>(ei, p, x, (float*)d_out, E, n, logn);
}